// round 4
// baseline (speedup 1.0000x reference)
#include <cuda_runtime.h>

#define NN 30000
#define EE 480000

// ---- device scratch (no allocs allowed) ----
__device__ float4 g_aggA[NN * 32];   // per node, 32 ch x {s_a, v_a.xyz}
__device__ float4 g_aggB[NN * 32];   // per node, 32 ch x {s_b, v_b.xyz}
__device__ float  g_x0[NN * 32];
__device__ float  g_x1[NN * 96];
__device__ int    g_count[NN];
__device__ int    g_offset[NN + 1];
__device__ int    g_cursor[NN];
__device__ int    g_sorted[EE];
__device__ int    g_dsts[EE];

// ---------------------------------------------------------------------------
// x0 = node_s @ W1_0 * inv_m ; x1[n,w,d] = sum_u node_v[n,u,d]*W1_1[u,w]*inv_m
// Also zeroes g_count.
__global__ void node_pre_kernel(const float* __restrict__ node_s,
                                const float* __restrict__ node_v,
                                const float* __restrict__ W1_0,
                                const float* __restrict__ W1_1) {
    __shared__ float w0s[1024], w1s[1024];
    for (int i = threadIdx.x; i < 1024; i += blockDim.x) {
        w0s[i] = W1_0[i];
        w1s[i] = W1_1[i];
    }
    __syncthreads();
    int warp = (blockIdx.x * blockDim.x + threadIdx.x) >> 5;
    int lane = threadIdx.x & 31;
    if (warp >= NN) return;
    if (lane == 0) g_count[warp] = 0;

    float s  = node_s[warp * 32 + lane];
    float v0 = node_v[warp * 96 + lane * 3 + 0];
    float v1 = node_v[warp * 96 + lane * 3 + 1];
    float v2 = node_v[warp * 96 + lane * 3 + 2];

    float x0 = 0.f, a0 = 0.f, a1 = 0.f, a2 = 0.f;
#pragma unroll
    for (int u = 0; u < 32; u++) {
        float su  = __shfl_sync(0xffffffffu, s,  u);
        float vu0 = __shfl_sync(0xffffffffu, v0, u);
        float vu1 = __shfl_sync(0xffffffffu, v1, u);
        float vu2 = __shfl_sync(0xffffffffu, v2, u);
        float w0 = w0s[u * 32 + lane];
        float w1 = w1s[u * 32 + lane];
        x0 = fmaf(su, w0, x0);
        a0 = fmaf(vu0, w1, a0);
        a1 = fmaf(vu1, w1, a1);
        a2 = fmaf(vu2, w1, a2);
    }
    const float inv_m = 0.17677669529663687f;  // 1/sqrt(32)
    g_x0[warp * 32 + lane]         = x0 * inv_m;
    g_x1[warp * 96 + lane * 3 + 0] = a0 * inv_m;
    g_x1[warp * 96 + lane * 3 + 1] = a1 * inv_m;
    g_x1[warp * 96 + lane * 3 + 2] = a2 * inv_m;
}

// ---------------------------------------------------------------------------
__global__ void hist_kernel(const int* __restrict__ edge_src) {
    int i = blockIdx.x * blockDim.x + threadIdx.x;
    if (i < EE) atomicAdd(&g_count[edge_src[i]], 1);
}

// Single-block exclusive scan of g_count -> g_offset / g_cursor.
__global__ void scan_kernel() {
    __shared__ int ps[1024];
    int tid = threadIdx.x;
    const int CH = 30;  // 1024*30 >= NN
    int base = tid * CH;
    int s = 0;
    for (int i = 0; i < CH; i++) {
        int idx = base + i;
        if (idx < NN) s += g_count[idx];
    }
    ps[tid] = s;
    __syncthreads();
    for (int off = 1; off < 1024; off <<= 1) {
        int t = (tid >= off) ? ps[tid - off] : 0;
        __syncthreads();
        ps[tid] += t;
        __syncthreads();
    }
    int run = ps[tid] - s;  // exclusive prefix
    for (int i = 0; i < CH; i++) {
        int idx = base + i;
        if (idx < NN) {
            g_offset[idx] = run;
            g_cursor[idx] = run;
            run += g_count[idx];
        }
    }
    if (tid == 0) g_offset[NN] = EE;
}

__global__ void scatter_kernel(const int* __restrict__ edge_src,
                               const int* __restrict__ edge_dst) {
    int i = blockIdx.x * blockDim.x + threadIdx.x;
    if (i < EE) {
        int s = edge_src[i];
        int d = edge_dst[i];
        int p = atomicAdd(&g_cursor[s], 1);
        g_sorted[p] = i;
        g_dsts[p] = d;
    }
}

// ---------------------------------------------------------------------------
// Warp per src node: walk CSR edge list, accumulate in registers, one store.
__global__ void edge_agg_kernel(const float* __restrict__ edge_attr,
                                const float* __restrict__ edge_scalars,
                                const float* __restrict__ Wfc1,
                                const float* __restrict__ Wfc2) {
    __shared__ float fc1s[64], fc2s[1024];
    for (int i = threadIdx.x; i < 64; i += blockDim.x) fc1s[i] = Wfc1[i];
    for (int i = threadIdx.x; i < 1024; i += blockDim.x) fc2s[i] = Wfc2[i];
    __syncthreads();

    int n = blockIdx.x * 8 + (threadIdx.x >> 5);
    int lane = threadIdx.x & 31;
    if (n >= NN) return;

    int beg = g_offset[n], end = g_offset[n + 1];

    float aA0 = 0.f, aA1 = 0.f, aA2 = 0.f, aA3 = 0.f;
    float aB0 = 0.f, aB1 = 0.f, aB2 = 0.f, aB3 = 0.f;

    const float inv8 = 0.35355339059327373f;        // 1/sqrt(8)
    const float INV_SQRT3 = 0.5773502691896258f;

    for (int i = beg; i < end; i++) {
        int e    = g_sorted[i];
        int dstn = g_dsts[i];

        // issue gathers + edge payload loads up front (overlap with MLP)
        float x0 = g_x0[dstn * 32 + lane];
        float y0 = g_x1[dstn * 96 + lane * 3 + 0];
        float y1 = g_x1[dstn * 96 + lane * 3 + 1];
        float y2 = g_x1[dstn * 96 + lane * 3 + 2];
        float sh0 = edge_attr[e * 4 + 0];
        float sh1 = edge_attr[e * 4 + 1];
        float sh2 = edge_attr[e * 4 + 2];
        float sh3 = edge_attr[e * 4 + 3];

        // --- h = ssp(es @ Wfc1 * inv8): lanes 0..7 compute one output each
        float hv = 0.f;
        if (lane < 8) {
            float acc = 0.f;
#pragma unroll
            for (int k = 0; k < 8; k++)
                acc = fmaf(edge_scalars[e * 8 + k], fc1s[k * 8 + lane], acc);
            acc *= inv8;
            float ex = __expf(-fabsf(acc));
            hv = fmaxf(acc, 0.f) + log1pf(ex) - 0.6931471805599453f;
        }
        float h[8];
#pragma unroll
        for (int j = 0; j < 8; j++) h[j] = __shfl_sync(0xffffffffu, hv, j);

        // --- w = h @ Wfc2 * inv8
        float w00 = 0.f, w01 = 0.f, w10 = 0.f, w11 = 0.f;
#pragma unroll
        for (int j = 0; j < 8; j++) {
            const float* r = &fc2s[j * 128 + lane];
            w00 = fmaf(h[j], r[0],  w00);
            w01 = fmaf(h[j], r[32], w01);
            w10 = fmaf(h[j], r[64], w10);
            w11 = fmaf(h[j], r[96], w11);
        }
        w00 *= inv8; w01 *= inv8; w10 *= inv8; w11 *= inv8;

        float s_a = w00 * x0 * sh0;
        float dot = fmaf(y0, sh1, fmaf(y1, sh2, y2 * sh3));
        float s_b = w11 * dot * INV_SQRT3;
        float p = w01 * x0;
        float q = w10 * sh0;

        aA0 += s_a;     aA1 += p * sh1; aA2 += p * sh2; aA3 += p * sh3;
        aB0 += s_b;     aB1 += q * y0;  aB2 += q * y1;  aB3 += q * y2;
    }

    g_aggA[n * 32 + lane] = make_float4(aA0, aA1, aA2, aA3);
    g_aggB[n * 32 + lane] = make_float4(aB0, aB1, aB2, aB3);
}

// ---------------------------------------------------------------------------
// node_post3 (fixed): 4 threads/node, 32 fp32 reg accumulators/thread, all
// weights staged in 80KB dynamic smem, broadcast LDS.128 reads.
//   sm[0:8192)        Wsc0 * c_sc      (32,8,32)
//   sm[8192:16384)    Wsc1 * c_sc
//   sm[16384:18432)   W2_0 * c_agg     (64,32)
//   sm[18432:20480)   W2_1 * c_agg
#define P3_WSC0 0
#define P3_WSC1 8192
#define P3_W20  16384
#define P3_W21  18432
#define P3_FLOATS 20480
#define P3_BYTES (P3_FLOATS * 4)

__global__ __launch_bounds__(256)
void node_post3_kernel(const float* __restrict__ node_s,
                       const float* __restrict__ node_v,
                       const float* __restrict__ node_attr,
                       const float* __restrict__ W2_0,
                       const float* __restrict__ W2_1,
                       const float* __restrict__ Wsc0,
                       const float* __restrict__ Wsc1,
                       float* __restrict__ out) {
    extern __shared__ float sm[];
    const float c_agg = 0.03125f;  // 1/sqrt(64)*1/sqrt(16)
    const float c_sc  = 0.0625f;   // 1/sqrt(32*8)
    int tid = threadIdx.x;
    for (int i = tid; i < 8192; i += 256) {
        sm[P3_WSC0 + i] = Wsc0[i] * c_sc;
        sm[P3_WSC1 + i] = Wsc1[i] * c_sc;
    }
    for (int i = tid; i < 2048; i += 256) {
        sm[P3_W20 + i] = W2_0[i] * c_agg;
        sm[P3_W21 + i] = W2_1[i] * c_agg;
    }
    __syncthreads();

    int n = blockIdx.x * 64 + (tid >> 2);
    int r = tid & 3;                 // 0 = scalar, 1..3 = vector component r-1
    if (n >= NN) return;

    // inputs for the self-connection part
    float in[32];
    if (r == 0) {
#pragma unroll
        for (int u = 0; u < 32; u++) in[u] = node_s[n * 32 + u];
    } else {
#pragma unroll
        for (int u = 0; u < 32; u++) in[u] = node_v[n * 96 + u * 3 + (r - 1)];
    }
    const float* sWsc = (r == 0) ? &sm[P3_WSC0] : &sm[P3_WSC1];
    const float* sW2  = (r == 0) ? &sm[P3_W20]  : &sm[P3_W21];

    float4 acc[8];
#pragma unroll
    for (int i = 0; i < 8; i++) acc[i] = make_float4(0.f, 0.f, 0.f, 0.f);

    // --- self-connection: acc[w] += (in[u]*attr[v]) * Wsc[u,v,w]
    for (int v = 0; v < 8; v++) {
        float av = node_attr[n * 8 + v];
#pragma unroll
        for (int u = 0; u < 32; u++) {
            float m = in[u] * av;
            const float4* W = (const float4*)&sWsc[u * 256 + v * 32];
#pragma unroll
            for (int w4 = 0; w4 < 8; w4++) {
                float4 wv = W[w4];
                acc[w4].x = fmaf(m, wv.x, acc[w4].x);
                acc[w4].y = fmaf(m, wv.y, acc[w4].y);
                acc[w4].z = fmaf(m, wv.z, acc[w4].z);
                acc[w4].w = fmaf(m, wv.w, acc[w4].w);
            }
        }
    }

    // --- aggregate part: acc[w] += aggA[u][r]*W2[u,w] + aggB[u][r]*W2[32+u,w]
#pragma unroll
    for (int u = 0; u < 32; u++) {
        float m = ((const float*)&g_aggA[n * 32 + u])[r];
        const float4* W = (const float4*)&sW2[u * 32];
#pragma unroll
        for (int w4 = 0; w4 < 8; w4++) {
            float4 wv = W[w4];
            acc[w4].x = fmaf(m, wv.x, acc[w4].x);
            acc[w4].y = fmaf(m, wv.y, acc[w4].y);
            acc[w4].z = fmaf(m, wv.z, acc[w4].z);
            acc[w4].w = fmaf(m, wv.w, acc[w4].w);
        }
    }
#pragma unroll
    for (int u = 0; u < 32; u++) {
        float m = ((const float*)&g_aggB[n * 32 + u])[r];
        const float4* W = (const float4*)&sW2[(32 + u) * 32];
#pragma unroll
        for (int w4 = 0; w4 < 8; w4++) {
            float4 wv = W[w4];
            acc[w4].x = fmaf(m, wv.x, acc[w4].x);
            acc[w4].y = fmaf(m, wv.y, acc[w4].y);
            acc[w4].z = fmaf(m, wv.z, acc[w4].z);
            acc[w4].w = fmaf(m, wv.w, acc[w4].w);
        }
    }

    // --- store
    if (r == 0) {
        float4* o4 = (float4*)(out + n * 128);
#pragma unroll
        for (int w4 = 0; w4 < 8; w4++) o4[w4] = acc[w4];
    } else {
        float* o = out + n * 128 + 32 + (r - 1);
#pragma unroll
        for (int w4 = 0; w4 < 8; w4++) {
            o[(w4 * 4 + 0) * 3] = acc[w4].x;
            o[(w4 * 4 + 1) * 3] = acc[w4].y;
            o[(w4 * 4 + 2) * 3] = acc[w4].z;
            o[(w4 * 4 + 3) * 3] = acc[w4].w;
        }
    }
}

// ---------------------------------------------------------------------------
extern "C" void kernel_launch(void* const* d_in, const int* in_sizes, int n_in,
                              void* d_out, int out_size) {
    const float* node_s       = (const float*)d_in[0];
    const float* node_v       = (const float*)d_in[1];
    const float* node_attr    = (const float*)d_in[2];
    const float* edge_attr    = (const float*)d_in[3];
    const float* edge_scalars = (const float*)d_in[4];
    const float* W1_0         = (const float*)d_in[5];
    const float* W1_1         = (const float*)d_in[6];
    const float* Wfc1         = (const float*)d_in[7];
    const float* Wfc2         = (const float*)d_in[8];
    const float* W2_0         = (const float*)d_in[9];
    const float* W2_1         = (const float*)d_in[10];
    const float* Wsc0         = (const float*)d_in[11];
    const float* Wsc1         = (const float*)d_in[12];
    const int*   edge_src     = (const int*)d_in[13];
    const int*   edge_dst     = (const int*)d_in[14];
    float* out = (float*)d_out;

    cudaFuncSetAttribute(node_post3_kernel,
                         cudaFuncAttributeMaxDynamicSharedMemorySize, P3_BYTES);

    node_pre_kernel<<<(NN * 32 + 255) / 256, 256>>>(node_s, node_v, W1_0, W1_1);
    hist_kernel<<<(EE + 255) / 256, 256>>>(edge_src);
    scan_kernel<<<1, 1024>>>();
    scatter_kernel<<<(EE + 255) / 256, 256>>>(edge_src, edge_dst);
    edge_agg_kernel<<<(NN + 7) / 8, 256>>>(edge_attr, edge_scalars, Wfc1, Wfc2);
    node_post3_kernel<<<(NN + 63) / 64, 256, P3_BYTES>>>(node_s, node_v,
                                                         node_attr, W2_0, W2_1,
                                                         Wsc0, Wsc1, out);
}

// round 5
// speedup vs baseline: 1.9558x; 1.9558x over previous
#include <cuda_runtime.h>

#define NN 30000
#define EE 480000

// ---- device scratch (no allocs allowed) ----
__device__ float4 g_aggA[NN * 32];   // per node, 32 ch x {s_a, v_a.xyz}
__device__ float4 g_aggB[NN * 32];   // per node, 32 ch x {s_b, v_b.xyz}
__device__ float  g_x0[NN * 32];
__device__ float  g_x1[NN * 96];

// ---------------------------------------------------------------------------
__global__ void zero_kernel() {
    int i = blockIdx.x * blockDim.x + threadIdx.x;
    int stride = gridDim.x * blockDim.x;
    float4 z = make_float4(0.f, 0.f, 0.f, 0.f);
    for (int k = i; k < NN * 32; k += stride) {
        g_aggA[k] = z;
        g_aggB[k] = z;
    }
}

// ---------------------------------------------------------------------------
// x0 = node_s @ W1_0 * inv_m ; x1[n,w,d] = sum_u node_v[n,u,d]*W1_1[u,w]*inv_m
__global__ void node_pre_kernel(const float* __restrict__ node_s,
                                const float* __restrict__ node_v,
                                const float* __restrict__ W1_0,
                                const float* __restrict__ W1_1) {
    __shared__ float w0s[1024], w1s[1024];
    for (int i = threadIdx.x; i < 1024; i += blockDim.x) {
        w0s[i] = W1_0[i];
        w1s[i] = W1_1[i];
    }
    __syncthreads();
    int warp = (blockIdx.x * blockDim.x + threadIdx.x) >> 5;
    int lane = threadIdx.x & 31;
    if (warp >= NN) return;

    float s  = node_s[warp * 32 + lane];
    float v0 = node_v[warp * 96 + lane * 3 + 0];
    float v1 = node_v[warp * 96 + lane * 3 + 1];
    float v2 = node_v[warp * 96 + lane * 3 + 2];

    float x0 = 0.f, a0 = 0.f, a1 = 0.f, a2 = 0.f;
#pragma unroll
    for (int u = 0; u < 32; u++) {
        float su  = __shfl_sync(0xffffffffu, s,  u);
        float vu0 = __shfl_sync(0xffffffffu, v0, u);
        float vu1 = __shfl_sync(0xffffffffu, v1, u);
        float vu2 = __shfl_sync(0xffffffffu, v2, u);
        float w0 = w0s[u * 32 + lane];
        float w1 = w1s[u * 32 + lane];
        x0 = fmaf(su, w0, x0);
        a0 = fmaf(vu0, w1, a0);
        a1 = fmaf(vu1, w1, a1);
        a2 = fmaf(vu2, w1, a2);
    }
    const float inv_m = 0.17677669529663687f;  // 1/sqrt(32)
    g_x0[warp * 32 + lane]         = x0 * inv_m;
    g_x1[warp * 96 + lane * 3 + 0] = a0 * inv_m;
    g_x1[warp * 96 + lane * 3 + 1] = a1 * inv_m;
    g_x1[warp * 96 + lane * 3 + 2] = a2 * inv_m;
}

// ---------------------------------------------------------------------------
__device__ __forceinline__ void red_v4(float4* addr, float a, float b, float c, float d) {
    asm volatile("red.global.add.v4.f32 [%0], {%1,%2,%3,%4};"
                 :: "l"(addr), "f"(a), "f"(b), "f"(c), "f"(d) : "memory");
}

// One warp per edge; lane = channel u (0..31).  (R1's measured kernel.)
__global__ void edge_kernel(const float* __restrict__ edge_attr,
                            const float* __restrict__ edge_scalars,
                            const float* __restrict__ Wfc1,
                            const float* __restrict__ Wfc2,
                            const int*   __restrict__ edge_src,
                            const int*   __restrict__ edge_dst) {
    __shared__ float fc1s[64], fc2s[1024];
    for (int i = threadIdx.x; i < 64; i += blockDim.x) fc1s[i] = Wfc1[i];
    for (int i = threadIdx.x; i < 1024; i += blockDim.x) fc2s[i] = Wfc2[i];
    __syncthreads();

    int e = (blockIdx.x * blockDim.x + threadIdx.x) >> 5;
    int lane = threadIdx.x & 31;
    if (e >= EE) return;

    const float inv8 = 0.35355339059327373f;  // 1/sqrt(8)

    float hv = 0.f;
    if (lane < 8) {
        float acc = 0.f;
#pragma unroll
        for (int k = 0; k < 8; k++)
            acc = fmaf(edge_scalars[e * 8 + k], fc1s[k * 8 + lane], acc);
        acc *= inv8;
        float ex = __expf(-fabsf(acc));
        hv = fmaxf(acc, 0.f) + log1pf(ex) - 0.6931471805599453f;
    }
    float h[8];
#pragma unroll
    for (int j = 0; j < 8; j++) h[j] = __shfl_sync(0xffffffffu, hv, j);

    float w00 = 0.f, w01 = 0.f, w10 = 0.f, w11 = 0.f;
#pragma unroll
    for (int j = 0; j < 8; j++) {
        const float* r = &fc2s[j * 128 + lane];
        w00 = fmaf(h[j], r[0],  w00);
        w01 = fmaf(h[j], r[32], w01);
        w10 = fmaf(h[j], r[64], w10);
        w11 = fmaf(h[j], r[96], w11);
    }
    w00 *= inv8; w01 *= inv8; w10 *= inv8; w11 *= inv8;

    int dstn = edge_dst[e];
    int srcn = edge_src[e];

    float x0 = g_x0[dstn * 32 + lane];
    float y0 = g_x1[dstn * 96 + lane * 3 + 0];
    float y1 = g_x1[dstn * 96 + lane * 3 + 1];
    float y2 = g_x1[dstn * 96 + lane * 3 + 2];

    float sh0 = edge_attr[e * 4 + 0];
    float sh1 = edge_attr[e * 4 + 1];
    float sh2 = edge_attr[e * 4 + 2];
    float sh3 = edge_attr[e * 4 + 3];

    const float INV_SQRT3 = 0.5773502691896258f;
    float s_a = w00 * x0 * sh0;
    float dot = fmaf(y0, sh1, fmaf(y1, sh2, y2 * sh3));
    float s_b = w11 * dot * INV_SQRT3;
    float p = w01 * x0;
    float q = w10 * sh0;

    red_v4(&g_aggA[srcn * 32 + lane], s_a, p * sh1, p * sh2, p * sh3);
    red_v4(&g_aggB[srcn * 32 + lane], s_b, q * y0, q * y1, q * y2);
}

// ---------------------------------------------------------------------------
// node_post4: lane = output channel w, 2 nodes per warp, rolled u loop.
// smem (floats):
//   [0:4096)      Wsc0 lo:  float4 over v0..3 at (u*32+w)         * c_sc
//   [4096:8192)   Wsc0 hi:  float4 over v4..7
//   [8192:12288)  Wsc1 lo
//   [12288:16384) Wsc1 hi
//   [16384:18432) W2_0 * c_agg   (k*32+w)
//   [18432:20480) W2_1 * c_agg
#define P4_W0LO 0
#define P4_W0HI 4096
#define P4_W1LO 8192
#define P4_W1HI 12288
#define P4_W20  16384
#define P4_W21  18432
#define P4_FLOATS 20480
#define P4_BYTES (P4_FLOATS * 4)
#define P4_TILES 1875   /* 30000 / 16 nodes per block-tile */

__global__ __launch_bounds__(256)
void node_post4_kernel(const float* __restrict__ node_s,
                       const float* __restrict__ node_v,
                       const float* __restrict__ node_attr,
                       const float* __restrict__ W2_0,
                       const float* __restrict__ W2_1,
                       const float* __restrict__ Wsc0,
                       const float* __restrict__ Wsc1,
                       float* __restrict__ out) {
    extern __shared__ float sm[];
    const float c_agg = 0.03125f;  // 1/sqrt(64)*1/sqrt(16)
    const float c_sc  = 0.0625f;   // 1/sqrt(32*8)
    int tid = threadIdx.x;

    // stage + transpose weights once per block
    for (int i = tid; i < 8192; i += 256) {
        int u = i >> 8, v = (i >> 5) & 7, w = i & 31;
        int base = (u * 32 + w) * 4 + (v & 3);
        int lo = (v < 4);
        sm[(lo ? P4_W0LO : P4_W0HI) + base] = Wsc0[i] * c_sc;
        sm[(lo ? P4_W1LO : P4_W1HI) + base] = Wsc1[i] * c_sc;
    }
    for (int i = tid; i < 2048; i += 256) {
        sm[P4_W20 + i] = W2_0[i] * c_agg;
        sm[P4_W21 + i] = W2_1[i] * c_agg;
    }
    __syncthreads();

    int wid = tid >> 5, lane = tid & 31;

    for (int tile = blockIdx.x; tile < P4_TILES; tile += gridDim.x) {
        int n0 = tile * 16 + wid * 2;
        int n1 = n0 + 1;

        float s0 = node_s[n0 * 32 + lane];
        float s1 = node_s[n1 * 32 + lane];
        float v00 = node_v[n0 * 96 + lane * 3 + 0];
        float v01 = node_v[n0 * 96 + lane * 3 + 1];
        float v02 = node_v[n0 * 96 + lane * 3 + 2];
        float v10 = node_v[n1 * 96 + lane * 3 + 0];
        float v11 = node_v[n1 * 96 + lane * 3 + 1];
        float v12 = node_v[n1 * 96 + lane * 3 + 2];
        float4 a0lo = ((const float4*)(node_attr + n0 * 8))[0];
        float4 a0hi = ((const float4*)(node_attr + n0 * 8))[1];
        float4 a1lo = ((const float4*)(node_attr + n1 * 8))[0];
        float4 a1hi = ((const float4*)(node_attr + n1 * 8))[1];

        float accS0 = 0.f, aV00 = 0.f, aV01 = 0.f, aV02 = 0.f;
        float accS1 = 0.f, aV10 = 0.f, aV11 = 0.f, aV12 = 0.f;

#pragma unroll 4
        for (int u = 0; u < 32; u++) {
            float su0 = __shfl_sync(0xffffffffu, s0, u);
            float su1 = __shfl_sync(0xffffffffu, s1, u);
            float wv00 = __shfl_sync(0xffffffffu, v00, u);
            float wv01 = __shfl_sync(0xffffffffu, v01, u);
            float wv02 = __shfl_sync(0xffffffffu, v02, u);
            float wv10 = __shfl_sync(0xffffffffu, v10, u);
            float wv11 = __shfl_sync(0xffffffffu, v11, u);
            float wv12 = __shfl_sync(0xffffffffu, v12, u);

            int o = (u * 32 + lane) * 4;
            float4 c0 = *(const float4*)&sm[P4_W0LO + o];
            float4 c1 = *(const float4*)&sm[P4_W0HI + o];
            float4 d0 = *(const float4*)&sm[P4_W1LO + o];
            float4 d1 = *(const float4*)&sm[P4_W1HI + o];

            float A00 = a0lo.x * c0.x;
            A00 = fmaf(a0lo.y, c0.y, A00); A00 = fmaf(a0lo.z, c0.z, A00);
            A00 = fmaf(a0lo.w, c0.w, A00); A00 = fmaf(a0hi.x, c1.x, A00);
            A00 = fmaf(a0hi.y, c1.y, A00); A00 = fmaf(a0hi.z, c1.z, A00);
            A00 = fmaf(a0hi.w, c1.w, A00);
            float A01 = a1lo.x * c0.x;
            A01 = fmaf(a1lo.y, c0.y, A01); A01 = fmaf(a1lo.z, c0.z, A01);
            A01 = fmaf(a1lo.w, c0.w, A01); A01 = fmaf(a1hi.x, c1.x, A01);
            A01 = fmaf(a1hi.y, c1.y, A01); A01 = fmaf(a1hi.z, c1.z, A01);
            A01 = fmaf(a1hi.w, c1.w, A01);
            float A10 = a0lo.x * d0.x;
            A10 = fmaf(a0lo.y, d0.y, A10); A10 = fmaf(a0lo.z, d0.z, A10);
            A10 = fmaf(a0lo.w, d0.w, A10); A10 = fmaf(a0hi.x, d1.x, A10);
            A10 = fmaf(a0hi.y, d1.y, A10); A10 = fmaf(a0hi.z, d1.z, A10);
            A10 = fmaf(a0hi.w, d1.w, A10);
            float A11 = a1lo.x * d0.x;
            A11 = fmaf(a1lo.y, d0.y, A11); A11 = fmaf(a1lo.z, d0.z, A11);
            A11 = fmaf(a1lo.w, d0.w, A11); A11 = fmaf(a1hi.x, d1.x, A11);
            A11 = fmaf(a1hi.y, d1.y, A11); A11 = fmaf(a1hi.z, d1.z, A11);
            A11 = fmaf(a1hi.w, d1.w, A11);

            accS0 = fmaf(su0, A00, accS0);
            accS1 = fmaf(su1, A01, accS1);
            aV00 = fmaf(wv00, A10, aV00);
            aV01 = fmaf(wv01, A10, aV01);
            aV02 = fmaf(wv02, A10, aV02);
            aV10 = fmaf(wv10, A11, aV10);
            aV11 = fmaf(wv11, A11, aV11);
            aV12 = fmaf(wv12, A11, aV12);
        }

#pragma unroll 4
        for (int k = 0; k < 32; k++) {
            float4 qa = g_aggA[n0 * 32 + k];
            float4 qb = g_aggA[n1 * 32 + k];
            float t0 = sm[P4_W20 + k * 32 + lane];
            float t1 = sm[P4_W21 + k * 32 + lane];
            accS0 = fmaf(qa.x, t0, accS0);
            aV00 = fmaf(qa.y, t1, aV00);
            aV01 = fmaf(qa.z, t1, aV01);
            aV02 = fmaf(qa.w, t1, aV02);
            accS1 = fmaf(qb.x, t0, accS1);
            aV10 = fmaf(qb.y, t1, aV10);
            aV11 = fmaf(qb.z, t1, aV11);
            aV12 = fmaf(qb.w, t1, aV12);
        }
#pragma unroll 4
        for (int k = 0; k < 32; k++) {
            float4 qa = g_aggB[n0 * 32 + k];
            float4 qb = g_aggB[n1 * 32 + k];
            float t0 = sm[P4_W20 + (32 + k) * 32 + lane];
            float t1 = sm[P4_W21 + (32 + k) * 32 + lane];
            accS0 = fmaf(qa.x, t0, accS0);
            aV00 = fmaf(qa.y, t1, aV00);
            aV01 = fmaf(qa.z, t1, aV01);
            aV02 = fmaf(qa.w, t1, aV02);
            accS1 = fmaf(qb.x, t0, accS1);
            aV10 = fmaf(qb.y, t1, aV10);
            aV11 = fmaf(qb.z, t1, aV11);
            aV12 = fmaf(qb.w, t1, aV12);
        }

        out[n0 * 128 + lane] = accS0;
        out[n0 * 128 + 32 + lane * 3 + 0] = aV00;
        out[n0 * 128 + 32 + lane * 3 + 1] = aV01;
        out[n0 * 128 + 32 + lane * 3 + 2] = aV02;
        out[n1 * 128 + lane] = accS1;
        out[n1 * 128 + 32 + lane * 3 + 0] = aV10;
        out[n1 * 128 + 32 + lane * 3 + 1] = aV11;
        out[n1 * 128 + 32 + lane * 3 + 2] = aV12;
    }
}

// ---------------------------------------------------------------------------
extern "C" void kernel_launch(void* const* d_in, const int* in_sizes, int n_in,
                              void* d_out, int out_size) {
    const float* node_s       = (const float*)d_in[0];
    const float* node_v       = (const float*)d_in[1];
    const float* node_attr    = (const float*)d_in[2];
    const float* edge_attr    = (const float*)d_in[3];
    const float* edge_scalars = (const float*)d_in[4];
    const float* W1_0         = (const float*)d_in[5];
    const float* W1_1         = (const float*)d_in[6];
    const float* Wfc1         = (const float*)d_in[7];
    const float* Wfc2         = (const float*)d_in[8];
    const float* W2_0         = (const float*)d_in[9];
    const float* W2_1         = (const float*)d_in[10];
    const float* Wsc0         = (const float*)d_in[11];
    const float* Wsc1         = (const float*)d_in[12];
    const int*   edge_src     = (const int*)d_in[13];
    const int*   edge_dst     = (const int*)d_in[14];
    float* out = (float*)d_out;

    cudaFuncSetAttribute(node_post4_kernel,
                         cudaFuncAttributeMaxDynamicSharedMemorySize, P4_BYTES);

    zero_kernel<<<2048, 256>>>();
    node_pre_kernel<<<(NN * 32 + 255) / 256, 256>>>(node_s, node_v, W1_0, W1_1);
    edge_kernel<<<(EE * 32 + 255) / 256, 256>>>(edge_attr, edge_scalars, Wfc1, Wfc2,
                                                edge_src, edge_dst);
    node_post4_kernel<<<296, 256, P4_BYTES>>>(node_s, node_v, node_attr,
                                              W2_0, W2_1, Wsc0, Wsc1, out);
}

// round 6
// speedup vs baseline: 2.1211x; 1.0845x over previous
#include <cuda_runtime.h>

#define NN 30000
#define EE 480000

// ---- device scratch (no allocs allowed) ----
__device__ float4 g_aggA[NN * 32];   // per node, 32 ch x {s_a, v_a.xyz}
__device__ float4 g_aggB[NN * 32];   // per node, 32 ch x {s_b, v_b.xyz}
__device__ float  g_x0[NN * 32];
__device__ float  g_x1[NN * 96];     // planar: [n*96 + d*32 + u]
__device__ int    g_count[NN];
__device__ int    g_offset[NN + 1];
__device__ int    g_cursor[NN];
__device__ int    g_sorted[EE];
__device__ int    g_dsts[EE];
__device__ float  g_h[EE * 8];       // sorted order
__device__ float4 g_sh4[EE];         // sorted order

// ---------------------------------------------------------------------------
// x0 = node_s @ W1_0 * inv_m ; x1 planar. Also zeroes g_count.
__global__ void node_pre_kernel(const float* __restrict__ node_s,
                                const float* __restrict__ node_v,
                                const float* __restrict__ W1_0,
                                const float* __restrict__ W1_1) {
    __shared__ float w0s[1024], w1s[1024];
    for (int i = threadIdx.x; i < 1024; i += blockDim.x) {
        w0s[i] = W1_0[i];
        w1s[i] = W1_1[i];
    }
    __syncthreads();
    int warp = (blockIdx.x * blockDim.x + threadIdx.x) >> 5;
    int lane = threadIdx.x & 31;
    if (warp >= NN) return;
    if (lane == 0) g_count[warp] = 0;

    float s  = node_s[warp * 32 + lane];
    float v0 = node_v[warp * 96 + lane * 3 + 0];
    float v1 = node_v[warp * 96 + lane * 3 + 1];
    float v2 = node_v[warp * 96 + lane * 3 + 2];

    float x0 = 0.f, a0 = 0.f, a1 = 0.f, a2 = 0.f;
#pragma unroll
    for (int u = 0; u < 32; u++) {
        float su  = __shfl_sync(0xffffffffu, s,  u);
        float vu0 = __shfl_sync(0xffffffffu, v0, u);
        float vu1 = __shfl_sync(0xffffffffu, v1, u);
        float vu2 = __shfl_sync(0xffffffffu, v2, u);
        float w0 = w0s[u * 32 + lane];
        float w1 = w1s[u * 32 + lane];
        x0 = fmaf(su, w0, x0);
        a0 = fmaf(vu0, w1, a0);
        a1 = fmaf(vu1, w1, a1);
        a2 = fmaf(vu2, w1, a2);
    }
    const float inv_m = 0.17677669529663687f;  // 1/sqrt(32)
    g_x0[warp * 32 + lane]           = x0 * inv_m;
    g_x1[warp * 96 + 0 * 32 + lane]  = a0 * inv_m;
    g_x1[warp * 96 + 1 * 32 + lane]  = a1 * inv_m;
    g_x1[warp * 96 + 2 * 32 + lane]  = a2 * inv_m;
}

// ---------------------------------------------------------------------------
__global__ void hist_kernel(const int* __restrict__ edge_src) {
    int i = blockIdx.x * blockDim.x + threadIdx.x;
    if (i < EE) atomicAdd(&g_count[edge_src[i]], 1);
}

__global__ void scan_kernel() {
    __shared__ int ps[1024];
    int tid = threadIdx.x;
    const int CH = 30;  // 1024*30 >= NN
    int base = tid * CH;
    int s = 0;
    for (int i = 0; i < CH; i++) {
        int idx = base + i;
        if (idx < NN) s += g_count[idx];
    }
    ps[tid] = s;
    __syncthreads();
    for (int off = 1; off < 1024; off <<= 1) {
        int t = (tid >= off) ? ps[tid - off] : 0;
        __syncthreads();
        ps[tid] += t;
        __syncthreads();
    }
    int run = ps[tid] - s;
    for (int i = 0; i < CH; i++) {
        int idx = base + i;
        if (idx < NN) {
            g_offset[idx] = run;
            g_cursor[idx] = run;
            run += g_count[idx];
        }
    }
    if (tid == 0) g_offset[NN] = EE;
}

__global__ void scatter_kernel(const int* __restrict__ edge_src,
                               const int* __restrict__ edge_dst) {
    int i = blockIdx.x * blockDim.x + threadIdx.x;
    if (i < EE) {
        int s = edge_src[i];
        int d = edge_dst[i];
        int p = atomicAdd(&g_cursor[s], 1);
        g_sorted[p] = i;
        g_dsts[p] = d;
    }
}

// ---------------------------------------------------------------------------
// Thread per sorted edge slot: compute h[8] = ssp(es @ Wfc1 * inv8),
// pre-gather sh into sorted order.
__global__ void edge_h_kernel(const float* __restrict__ edge_scalars,
                              const float* __restrict__ edge_attr,
                              const float* __restrict__ Wfc1) {
    __shared__ float fc1s[64];
    if (threadIdx.x < 64) fc1s[threadIdx.x] = Wfc1[threadIdx.x];
    __syncthreads();
    int i = blockIdx.x * blockDim.x + threadIdx.x;
    if (i >= EE) return;
    int e = g_sorted[i];

    float4 e0 = ((const float4*)(edge_scalars + e * 8))[0];
    float4 e1 = ((const float4*)(edge_scalars + e * 8))[1];
    float es[8] = {e0.x, e0.y, e0.z, e0.w, e1.x, e1.y, e1.z, e1.w};

    const float inv8 = 0.35355339059327373f;  // 1/sqrt(8)
    float h[8];
#pragma unroll
    for (int j = 0; j < 8; j++) {
        float acc = 0.f;
#pragma unroll
        for (int k = 0; k < 8; k++)
            acc = fmaf(es[k], fc1s[k * 8 + j], acc);
        acc *= inv8;
        float ex = __expf(-fabsf(acc));
        h[j] = fmaxf(acc, 0.f) + log1pf(ex) - 0.6931471805599453f;
    }
    ((float4*)(g_h + i * 8))[0] = make_float4(h[0], h[1], h[2], h[3]);
    ((float4*)(g_h + i * 8))[1] = make_float4(h[4], h[5], h[6], h[7]);
    g_sh4[i] = *(const float4*)(edge_attr + e * 4);
}

// ---------------------------------------------------------------------------
// Warp per src node, 1-deep software pipeline on all loads; no atomics.
__global__ __launch_bounds__(256)
void edge_agg2_kernel(const float* __restrict__ Wfc2) {
    __shared__ float fc2s[1024];
    for (int i = threadIdx.x; i < 1024; i += blockDim.x) fc2s[i] = Wfc2[i];
    __syncthreads();

    int n = blockIdx.x * 8 + (threadIdx.x >> 5);
    int lane = threadIdx.x & 31;
    if (n >= NN) return;

    int beg = g_offset[n], end = g_offset[n + 1];

    float aA0 = 0.f, aA1 = 0.f, aA2 = 0.f, aA3 = 0.f;
    float aB0 = 0.f, aB1 = 0.f, aB2 = 0.f, aB3 = 0.f;

    const float inv8 = 0.35355339059327373f;
    const float INV_SQRT3 = 0.5773502691896258f;

    float4 h0_c, h1_c, sh_c;
    float x0_c = 0.f, y0_c = 0.f, y1_c = 0.f, y2_c = 0.f;
    h0_c = make_float4(0.f, 0.f, 0.f, 0.f);
    h1_c = h0_c; sh_c = h0_c;

    if (beg < end) {
        h0_c = ((const float4*)(g_h + beg * 8))[0];
        h1_c = ((const float4*)(g_h + beg * 8))[1];
        sh_c = g_sh4[beg];
        int d = g_dsts[beg];
        x0_c = g_x0[d * 32 + lane];
        y0_c = g_x1[d * 96 + 0 * 32 + lane];
        y1_c = g_x1[d * 96 + 1 * 32 + lane];
        y2_c = g_x1[d * 96 + 2 * 32 + lane];
    }

    for (int i = beg; i < end; i++) {
        float4 h0 = h0_c, h1 = h1_c, sh = sh_c;
        float x0 = x0_c, y0 = y0_c, y1 = y1_c, y2 = y2_c;

        // issue next iteration's loads before computing
        if (i + 1 < end) {
            h0_c = ((const float4*)(g_h + (i + 1) * 8))[0];
            h1_c = ((const float4*)(g_h + (i + 1) * 8))[1];
            sh_c = g_sh4[i + 1];
            int d = g_dsts[i + 1];
            x0_c = g_x0[d * 32 + lane];
            y0_c = g_x1[d * 96 + 0 * 32 + lane];
            y1_c = g_x1[d * 96 + 1 * 32 + lane];
            y2_c = g_x1[d * 96 + 2 * 32 + lane];
        }

        // w = h @ Wfc2 * inv8 (columns lane, lane+32, lane+64, lane+96)
        const float* r0 = &fc2s[lane];
        float w00, w01, w10, w11;
        w00 = h0.x * r0[0];
        w00 = fmaf(h0.y, r0[128], w00); w00 = fmaf(h0.z, r0[256], w00);
        w00 = fmaf(h0.w, r0[384], w00); w00 = fmaf(h1.x, r0[512], w00);
        w00 = fmaf(h1.y, r0[640], w00); w00 = fmaf(h1.z, r0[768], w00);
        w00 = fmaf(h1.w, r0[896], w00);
        const float* r1 = r0 + 32;
        w01 = h0.x * r1[0];
        w01 = fmaf(h0.y, r1[128], w01); w01 = fmaf(h0.z, r1[256], w01);
        w01 = fmaf(h0.w, r1[384], w01); w01 = fmaf(h1.x, r1[512], w01);
        w01 = fmaf(h1.y, r1[640], w01); w01 = fmaf(h1.z, r1[768], w01);
        w01 = fmaf(h1.w, r1[896], w01);
        const float* r2 = r0 + 64;
        w10 = h0.x * r2[0];
        w10 = fmaf(h0.y, r2[128], w10); w10 = fmaf(h0.z, r2[256], w10);
        w10 = fmaf(h0.w, r2[384], w10); w10 = fmaf(h1.x, r2[512], w10);
        w10 = fmaf(h1.y, r2[640], w10); w10 = fmaf(h1.z, r2[768], w10);
        w10 = fmaf(h1.w, r2[896], w10);
        const float* r3 = r0 + 96;
        w11 = h0.x * r3[0];
        w11 = fmaf(h0.y, r3[128], w11); w11 = fmaf(h0.z, r3[256], w11);
        w11 = fmaf(h0.w, r3[384], w11); w11 = fmaf(h1.x, r3[512], w11);
        w11 = fmaf(h1.y, r3[640], w11); w11 = fmaf(h1.z, r3[768], w11);
        w11 = fmaf(h1.w, r3[896], w11);
        w00 *= inv8; w01 *= inv8; w10 *= inv8; w11 *= inv8;

        float s_a = w00 * x0 * sh.x;
        float dot = fmaf(y0, sh.y, fmaf(y1, sh.z, y2 * sh.w));
        float s_b = w11 * dot * INV_SQRT3;
        float p = w01 * x0;
        float q = w10 * sh.x;

        aA0 += s_a;    aA1 = fmaf(p, sh.y, aA1);
        aA2 = fmaf(p, sh.z, aA2);  aA3 = fmaf(p, sh.w, aA3);
        aB0 += s_b;    aB1 = fmaf(q, y0, aB1);
        aB2 = fmaf(q, y1, aB2);    aB3 = fmaf(q, y2, aB3);
    }

    g_aggA[n * 32 + lane] = make_float4(aA0, aA1, aA2, aA3);
    g_aggB[n * 32 + lane] = make_float4(aB0, aB1, aB2, aB3);
}

// ---------------------------------------------------------------------------
// node_post4b: lane = output channel w, 2 nodes per warp, rolled u loop.
// Wsc staged in 64KB dynamic smem (3 blocks/SM); W2 read via L1 LDG.
#define P4_W0LO 0
#define P4_W0HI 4096
#define P4_W1LO 8192
#define P4_W1HI 12288
#define P4_FLOATS 16384
#define P4_BYTES (P4_FLOATS * 4)
#define P4_TILES 1875   /* 30000 / 16 nodes per block-tile */

__global__ __launch_bounds__(256)
void node_post4_kernel(const float* __restrict__ node_s,
                       const float* __restrict__ node_v,
                       const float* __restrict__ node_attr,
                       const float* __restrict__ W2_0,
                       const float* __restrict__ W2_1,
                       const float* __restrict__ Wsc0,
                       const float* __restrict__ Wsc1,
                       float* __restrict__ out) {
    extern __shared__ float sm[];
    const float c_agg = 0.03125f;  // 1/sqrt(64)*1/sqrt(16)
    const float c_sc  = 0.0625f;   // 1/sqrt(32*8)
    int tid = threadIdx.x;

    for (int i = tid; i < 8192; i += 256) {
        int u = i >> 8, v = (i >> 5) & 7, w = i & 31;
        int base = (u * 32 + w) * 4 + (v & 3);
        int lo = (v < 4);
        sm[(lo ? P4_W0LO : P4_W0HI) + base] = Wsc0[i] * c_sc;
        sm[(lo ? P4_W1LO : P4_W1HI) + base] = Wsc1[i] * c_sc;
    }
    __syncthreads();

    int wid = tid >> 5, lane = tid & 31;

    for (int tile = blockIdx.x; tile < P4_TILES; tile += gridDim.x) {
        int n0 = tile * 16 + wid * 2;
        int n1 = n0 + 1;

        float s0 = node_s[n0 * 32 + lane];
        float s1 = node_s[n1 * 32 + lane];
        float v00 = node_v[n0 * 96 + lane * 3 + 0];
        float v01 = node_v[n0 * 96 + lane * 3 + 1];
        float v02 = node_v[n0 * 96 + lane * 3 + 2];
        float v10 = node_v[n1 * 96 + lane * 3 + 0];
        float v11 = node_v[n1 * 96 + lane * 3 + 1];
        float v12 = node_v[n1 * 96 + lane * 3 + 2];
        float4 a0lo = ((const float4*)(node_attr + n0 * 8))[0];
        float4 a0hi = ((const float4*)(node_attr + n0 * 8))[1];
        float4 a1lo = ((const float4*)(node_attr + n1 * 8))[0];
        float4 a1hi = ((const float4*)(node_attr + n1 * 8))[1];

        float accS0 = 0.f, aV00 = 0.f, aV01 = 0.f, aV02 = 0.f;
        float accS1 = 0.f, aV10 = 0.f, aV11 = 0.f, aV12 = 0.f;

#pragma unroll 4
        for (int u = 0; u < 32; u++) {
            float su0 = __shfl_sync(0xffffffffu, s0, u);
            float su1 = __shfl_sync(0xffffffffu, s1, u);
            float wv00 = __shfl_sync(0xffffffffu, v00, u);
            float wv01 = __shfl_sync(0xffffffffu, v01, u);
            float wv02 = __shfl_sync(0xffffffffu, v02, u);
            float wv10 = __shfl_sync(0xffffffffu, v10, u);
            float wv11 = __shfl_sync(0xffffffffu, v11, u);
            float wv12 = __shfl_sync(0xffffffffu, v12, u);

            int o = (u * 32 + lane) * 4;
            float4 c0 = *(const float4*)&sm[P4_W0LO + o];
            float4 c1 = *(const float4*)&sm[P4_W0HI + o];
            float4 d0 = *(const float4*)&sm[P4_W1LO + o];
            float4 d1 = *(const float4*)&sm[P4_W1HI + o];

            float A00 = a0lo.x * c0.x;
            A00 = fmaf(a0lo.y, c0.y, A00); A00 = fmaf(a0lo.z, c0.z, A00);
            A00 = fmaf(a0lo.w, c0.w, A00); A00 = fmaf(a0hi.x, c1.x, A00);
            A00 = fmaf(a0hi.y, c1.y, A00); A00 = fmaf(a0hi.z, c1.z, A00);
            A00 = fmaf(a0hi.w, c1.w, A00);
            float A01 = a1lo.x * c0.x;
            A01 = fmaf(a1lo.y, c0.y, A01); A01 = fmaf(a1lo.z, c0.z, A01);
            A01 = fmaf(a1lo.w, c0.w, A01); A01 = fmaf(a1hi.x, c1.x, A01);
            A01 = fmaf(a1hi.y, c1.y, A01); A01 = fmaf(a1hi.z, c1.z, A01);
            A01 = fmaf(a1hi.w, c1.w, A01);
            float A10 = a0lo.x * d0.x;
            A10 = fmaf(a0lo.y, d0.y, A10); A10 = fmaf(a0lo.z, d0.z, A10);
            A10 = fmaf(a0lo.w, d0.w, A10); A10 = fmaf(a0hi.x, d1.x, A10);
            A10 = fmaf(a0hi.y, d1.y, A10); A10 = fmaf(a0hi.z, d1.z, A10);
            A10 = fmaf(a0hi.w, d1.w, A10);
            float A11 = a1lo.x * d0.x;
            A11 = fmaf(a1lo.y, d0.y, A11); A11 = fmaf(a1lo.z, d0.z, A11);
            A11 = fmaf(a1lo.w, d0.w, A11); A11 = fmaf(a1hi.x, d1.x, A11);
            A11 = fmaf(a1hi.y, d1.y, A11); A11 = fmaf(a1hi.z, d1.z, A11);
            A11 = fmaf(a1hi.w, d1.w, A11);

            accS0 = fmaf(su0, A00, accS0);
            accS1 = fmaf(su1, A01, accS1);
            aV00 = fmaf(wv00, A10, aV00);
            aV01 = fmaf(wv01, A10, aV01);
            aV02 = fmaf(wv02, A10, aV02);
            aV10 = fmaf(wv10, A11, aV10);
            aV11 = fmaf(wv11, A11, aV11);
            aV12 = fmaf(wv12, A11, aV12);
        }

#pragma unroll 4
        for (int k = 0; k < 32; k++) {
            float4 qa = g_aggA[n0 * 32 + k];
            float4 qb = g_aggA[n1 * 32 + k];
            float t0 = W2_0[k * 32 + lane] * c_agg;
            float t1 = W2_1[k * 32 + lane] * c_agg;
            accS0 = fmaf(qa.x, t0, accS0);
            aV00 = fmaf(qa.y, t1, aV00);
            aV01 = fmaf(qa.z, t1, aV01);
            aV02 = fmaf(qa.w, t1, aV02);
            accS1 = fmaf(qb.x, t0, accS1);
            aV10 = fmaf(qb.y, t1, aV10);
            aV11 = fmaf(qb.z, t1, aV11);
            aV12 = fmaf(qb.w, t1, aV12);
        }
#pragma unroll 4
        for (int k = 0; k < 32; k++) {
            float4 qa = g_aggB[n0 * 32 + k];
            float4 qb = g_aggB[n1 * 32 + k];
            float t0 = W2_0[(32 + k) * 32 + lane] * c_agg;
            float t1 = W2_1[(32 + k) * 32 + lane] * c_agg;
            accS0 = fmaf(qa.x, t0, accS0);
            aV00 = fmaf(qa.y, t1, aV00);
            aV01 = fmaf(qa.z, t1, aV01);
            aV02 = fmaf(qa.w, t1, aV02);
            accS1 = fmaf(qb.x, t0, accS1);
            aV10 = fmaf(qb.y, t1, aV10);
            aV11 = fmaf(qb.z, t1, aV11);
            aV12 = fmaf(qb.w, t1, aV12);
        }

        out[n0 * 128 + lane] = accS0;
        out[n0 * 128 + 32 + lane * 3 + 0] = aV00;
        out[n0 * 128 + 32 + lane * 3 + 1] = aV01;
        out[n0 * 128 + 32 + lane * 3 + 2] = aV02;
        out[n1 * 128 + lane] = accS1;
        out[n1 * 128 + 32 + lane * 3 + 0] = aV10;
        out[n1 * 128 + 32 + lane * 3 + 1] = aV11;
        out[n1 * 128 + 32 + lane * 3 + 2] = aV12;
    }
}

// ---------------------------------------------------------------------------
extern "C" void kernel_launch(void* const* d_in, const int* in_sizes, int n_in,
                              void* d_out, int out_size) {
    const float* node_s       = (const float*)d_in[0];
    const float* node_v       = (const float*)d_in[1];
    const float* node_attr    = (const float*)d_in[2];
    const float* edge_attr    = (const float*)d_in[3];
    const float* edge_scalars = (const float*)d_in[4];
    const float* W1_0         = (const float*)d_in[5];
    const float* W1_1         = (const float*)d_in[6];
    const float* Wfc1         = (const float*)d_in[7];
    const float* Wfc2         = (const float*)d_in[8];
    const float* W2_0         = (const float*)d_in[9];
    const float* W2_1         = (const float*)d_in[10];
    const float* Wsc0         = (const float*)d_in[11];
    const float* Wsc1         = (const float*)d_in[12];
    const int*   edge_src     = (const int*)d_in[13];
    const int*   edge_dst     = (const int*)d_in[14];
    float* out = (float*)d_out;

    cudaFuncSetAttribute(node_post4_kernel,
                         cudaFuncAttributeMaxDynamicSharedMemorySize, P4_BYTES);

    node_pre_kernel<<<(NN * 32 + 255) / 256, 256>>>(node_s, node_v, W1_0, W1_1);
    hist_kernel<<<(EE + 255) / 256, 256>>>(edge_src);
    scan_kernel<<<1, 1024>>>();
    scatter_kernel<<<(EE + 255) / 256, 256>>>(edge_src, edge_dst);
    edge_h_kernel<<<(EE + 255) / 256, 256>>>(edge_scalars, edge_attr, Wfc1);
    edge_agg2_kernel<<<(NN + 7) / 8, 256>>>(Wfc2);
    node_post4_kernel<<<444, 256, P4_BYTES>>>(node_s, node_v, node_attr,
                                              W2_0, W2_1, Wsc0, Wsc1, out);
}